// round 14
// baseline (speedup 1.0000x reference)
#include <cuda_runtime.h>
#include <cuda_bf16.h>

#define N_IN    11008
#define N_OUT   4096
#define TOPK_K  5504
#define N_CACHE 64
#define NBW     344            // ceil(11008/32)
#define TPB     1024
#define GRID    128            // 128 blocks x 32 warps = 4096 warps = 1 row/warp
#define PT      11             // elements per thread in select (1024*11 >= 11008)

// ---- device-global scratch (allocation-free; fully rewritten each call) ----
__device__ __align__(16) float g_xm[N_IN];
__device__ unsigned g_maskbits[NBW];
__device__ int g_inter[N_CACHE];
__device__ unsigned g_arrive;     // launch arrival counter (monotonic)
__device__ unsigned g_mask_done;  // +1 per launch when maskbits published
__device__ unsigned g_int_done;   // +64 per launch when intersections written
__device__ unsigned g_xm_done;    // +11 per launch when xm final

// Sleep-poll until *addr >= target (acquire).
__device__ __forceinline__ void poll_ge(const unsigned* addr, unsigned target) {
    unsigned cur;
    for (;;) {
        asm volatile("ld.acquire.gpu.u32 %0, [%1];"
                     : "=r"(cur) : "l"(addr) : "memory");
        if (cur >= target) break;
        __nanosleep(64);
    }
}

// 1024-thread block inclusive scan (one int per thread).
__device__ __forceinline__ int scan1024(int v, int lane, int wid, int* sbuf) {
    __syncthreads();
    #pragma unroll
    for (int o = 1; o < 32; o <<= 1) {
        int t = __shfl_up_sync(0xffffffffu, v, o);
        if (lane >= o) v += t;
    }
    if (lane == 31) sbuf[wid] = v;
    __syncthreads();
    if (wid == 0) {
        int w = sbuf[lane];
        #pragma unroll
        for (int o = 1; o < 32; o <<= 1) {
            int t = __shfl_up_sync(0xffffffffu, w, o);
            if (lane >= o) w += t;
        }
        sbuf[lane] = w;
    }
    __syncthreads();
    if (wid > 0) v += sbuf[wid - 1];
    return v;
}

// ============================================================================
// Mega-kernel, ONE launch, 128 blocks x 1024 threads, counter-released phases:
//   block 0:      register-resident radix select -> maskbits -> g_mask_done++
//   blocks 1..64: cbits (concurrent) -> poll mask -> intersection -> g_int_done++
//   blocks 0..10: poll int==64 -> decision -> xm chunk -> g_xm_done += 1 (or 11)
//   everyone:     poll xm==11 -> GEMV (1 row/warp, proven 5.3 TB/s pattern)
// ============================================================================
__global__ void __launch_bounds__(TPB, 1)
mega_kernel(const float* __restrict__ x, const int* __restrict__ cached,
            const float* __restrict__ W, const float* __restrict__ bias,
            float* __restrict__ out) {
    __shared__ unsigned s_mem[N_IN];     // block 0: |x| bits; blocks 1-64: cbits
    __shared__ unsigned hist[2048];
    __shared__ unsigned s_bits[NBW];
    __shared__ int scanbuf[32];
    __shared__ int s_b, s_G, s_need, s_use, s_best;
    __shared__ unsigned s_T, s_gen;

    const int b = blockIdx.x, tid = threadIdx.x;
    const int lane = tid & 31, wid = tid >> 5;

    if (tid == 0) s_gen = atomicAdd(&g_arrive, 1u) / GRID;   // launch generation
    __syncthreads();
    const unsigned gen = s_gen;

    if (b == 0) {
        // ---- fused coalesced stage + level-0 histogram (bits [30:21]) ----
        for (int i = tid; i < 2048; i += TPB) hist[i] = 0;
        for (int i = tid; i < NBW; i += TPB) s_bits[i] = 0;
        __syncthreads();
        for (int i = tid; i < N_IN; i += TPB) {
            unsigned u = __float_as_uint(x[i]) & 0x7FFFFFFFu;
            s_mem[i] = u;
            atomicAdd(&hist[u >> 21], 1u);
        }
        __syncthreads();

        // ---- pull this thread's 11 contiguous elements into registers ----
        unsigned v[PT];
        const int start = tid * PT;
        const int nel   = max(0, min(PT, N_IN - start));
        #pragma unroll
        for (int k = 0; k < PT; k++)
            v[k] = (k < nel) ? s_mem[start + k] : 0u;

        // ---- level 0 search ----
        {
            const int j0 = 2047 - 2 * tid, j1 = j0 - 1;
            const int h0 = hist[j0], h1 = hist[j1];
            int S = scan1024(h0 + h1, lane, wid, scanbuf);
            int excl = S - h0 - h1;
            const int Kr = TOPK_K;
            if (excl + h0 >= Kr && excl < Kr)   { s_b = j0; s_G = excl; }
            else if (S >= Kr && excl + h0 < Kr) { s_b = j1; s_G = excl + h0; }
        }
        __syncthreads();
        const int b0 = s_b, G0 = s_G;

        // ---- level 1: bits [20:10] (register source) ----
        __syncthreads();
        for (int i = tid; i < 2048; i += TPB) hist[i] = 0;
        __syncthreads();
        #pragma unroll
        for (int k = 0; k < PT; k++)
            if (k < nel && (int)(v[k] >> 21) == b0)
                atomicAdd(&hist[(v[k] >> 10) & 0x7FF], 1u);
        __syncthreads();
        {
            const int j0 = 2047 - 2 * tid, j1 = j0 - 1;
            const int h0 = hist[j0], h1 = hist[j1];
            int S = scan1024(h0 + h1, lane, wid, scanbuf);
            int excl = S - h0 - h1;
            const int Kr = TOPK_K - G0;
            if (excl + h0 >= Kr && excl < Kr)   { s_b = j0; s_G = G0 + excl; }
            else if (S >= Kr && excl + h0 < Kr) { s_b = j1; s_G = G0 + excl + h0; }
        }
        __syncthreads();
        const int b1 = s_b, G1 = s_G;

        // ---- level 2: bits [9:0] (register source) ----
        __syncthreads();
        for (int i = tid; i < 2048; i += TPB) hist[i] = 0;
        __syncthreads();
        const unsigned top22 = ((unsigned)b0 << 21) | ((unsigned)b1 << 10);
        #pragma unroll
        for (int k = 0; k < PT; k++)
            if (k < nel && (v[k] & 0xFFFFFC00u) == top22)
                atomicAdd(&hist[v[k] & 0x3FF], 1u);
        __syncthreads();
        {
            const int j = 1023 - tid;
            const int h = (int)hist[j];
            int S = scan1024(h, lane, wid, scanbuf);
            int excl = S - h;
            const int Kr = TOPK_K - G1;
            if (S >= Kr && excl < Kr) { s_T = top22 | (unsigned)j; s_need = Kr - excl; }
        }
        __syncthreads();
        const unsigned T = s_T;
        const int need = s_need;

        // ---- tie count + mask build (register source, index-ascending) ----
        int tieCnt = 0;
        #pragma unroll
        for (int k = 0; k < PT; k++)
            if (k < nel && v[k] == T) tieCnt++;
        int incl = scan1024(tieCnt, lane, wid, scanbuf);
        int rank = incl - tieCnt;

        #pragma unroll
        for (int k = 0; k < PT; k++) {
            if (k < nel) {
                unsigned u = v[k];
                bool sel;
                if (u > T)       sel = true;
                else if (u == T) { sel = (rank < need); rank++; }
                else             sel = false;
                if (sel) {
                    const int i = start + k;
                    atomicOr(&s_bits[i >> 5], 1u << (i & 31));
                }
            }
        }
        __syncthreads();
        for (int i = tid; i < NBW; i += TPB) g_maskbits[i] = s_bits[i];
        __syncthreads();
        if (tid == 0) {
            __threadfence();
            atomicAdd(&g_mask_done, 1u);            // release maskbits
        }
    } else if (b <= 64) {
        // ---- cache bitset for cache (b-1), fully concurrent with select ----
        for (int i = tid; i < NBW; i += TPB) s_mem[i] = 0;
        __syncthreads();
        const int* row = cached + (b - 1) * TOPK_K;
        for (int k = tid; k < TOPK_K; k += TPB) {
            int idx = row[k];
            atomicOr(&s_mem[idx >> 5], 1u << (idx & 31));
        }
        __syncthreads();

        if (tid == 0) poll_ge(&g_mask_done, gen + 1u);
        __syncthreads();

        // ---- deduped intersection ----
        int cnt = 0;
        for (int i = tid; i < NBW; i += TPB)
            cnt += __popc(s_mem[i] & g_maskbits[i]);
        #pragma unroll
        for (int o = 16; o; o >>= 1) cnt += __shfl_down_sync(0xffffffffu, cnt, o);
        __syncthreads();
        if (lane == 0) scanbuf[wid] = cnt;
        __syncthreads();
        if (tid == 0) {
            int s = 0;
            #pragma unroll
            for (int i = 0; i < 32; i++) s += scanbuf[i];
            g_inter[b - 1] = s;
            __threadfence();
            atomicAdd(&g_int_done, 1u);             // one of 64
        }
    }

    // ---- xm builders: blocks 0..10 ----
    if (b < 11) {
        if (tid == 0) poll_ge(&g_int_done, (gen + 1u) * 64u);
        __syncthreads();

        if (tid == 0) {
            float best = -1.0f; int bi = 0;
            #pragma unroll
            for (int i = 0; i < N_CACHE; i++) {
                float r = (float)g_inter[i] / (float)TOPK_K;
                if (r > best) { best = r; bi = i; }   // first-max = argmax
            }
            s_use  = (best >= 0.9f) ? 1 : 0;
            s_best = bi;
        }
        __syncthreads();

        if (!s_use) {
            // top-k path: build my 1024-wide chunk of xm
            const int gi = b * TPB + tid;
            if (gi < N_IN) {
                int sel = (g_maskbits[gi >> 5] >> (gi & 31)) & 1;
                g_xm[gi] = sel ? x[gi] : 0.0f;
            }
            __syncthreads();
            if (tid == 0) {
                __threadfence();
                atomicAdd(&g_xm_done, 1u);          // one of 11
            }
        } else if (b == 0) {
            // cache path (cold): block 0 builds the entire xm
            for (int i = tid; i < N_IN; i += TPB) g_xm[i] = 0.0f;
            __syncthreads();
            const int* brow = cached + s_best * TOPK_K;
            for (int k = tid; k < TOPK_K; k += TPB) {
                int idx = brow[k];
                atomicAdd(&g_xm[idx], x[idx]);      // duplicates = multiplicity
            }
            __syncthreads();
            if (tid == 0) {
                __threadfence();
                atomicAdd(&g_xm_done, 11u);         // full release
            }
        }
        // blocks 1..10 on cache path contribute nothing (block 0 adds all 11)
    }

    // ---- everyone waits for xm, then GEMV ----
    if (tid == 0) poll_ge(&g_xm_done, (gen + 1u) * 11u);
    __syncthreads();

    // ---- GEMV: exact R4 pattern — 1 row/warp, 4096 x 44KB streams ----
    const int row = b * 32 + wid;                // 0..4095
    const float4* __restrict__ w4 = (const float4*)(W + (long long)row * N_IN);
    const float4* __restrict__ x4 = (const float4*)g_xm;

    float a0 = 0.0f, a1 = 0.0f;
    #pragma unroll 4
    for (int it = 0; it < 43; it++) {
        const int j = lane + it * 64;
        float4 w  = __ldcs(w4 + j);
        float4 v  = x4[j];
        a0 += w.x * v.x + w.y * v.y;
        a1 += w.z * v.z + w.w * v.w;
        float4 w2 = __ldcs(w4 + j + 32);
        float4 v2 = x4[j + 32];
        a0 += w2.x * v2.x + w2.y * v2.y;
        a1 += w2.z * v2.z + w2.w * v2.w;
    }
    float acc = a0 + a1;
    #pragma unroll
    for (int o = 16; o; o >>= 1) acc += __shfl_down_sync(0xffffffffu, acc, o);
    if (lane == 0) out[row] = acc + bias[row];
}

// ============================================================================
extern "C" void kernel_launch(void* const* d_in, const int* in_sizes, int n_in,
                              void* d_out, int out_size) {
    const float* x      = (const float*)d_in[0];
    const float* W      = (const float*)d_in[1];
    const float* bias   = (const float*)d_in[2];
    const int*   cached = (const int*)d_in[3];
    float*       out    = (float*)d_out;

    mega_kernel<<<GRID, TPB>>>(x, cached, W, bias, out);
}

// round 15
// speedup vs baseline: 1.2247x; 1.2247x over previous
#include <cuda_runtime.h>
#include <cuda_bf16.h>

#define N_IN    11008
#define N_OUT   4096
#define TOPK_K  5504
#define N_CACHE 64
#define NBW     344            // ceil(11008/32)
#define TPB     1024
#define GRID    128            // 128 blocks x 32 warps = 4096 warps = 1 row/warp

// ---- device-global scratch (allocation-free; fully rewritten each call) ----
__device__ __align__(16) float g_xm[N_IN];
__device__ unsigned g_maskbits[NBW];
__device__ int g_inter[N_CACHE];
__device__ unsigned g_arrive;     // launch arrival counter (monotonic)
__device__ unsigned g_mask_done;  // +1  per launch: maskbits published
__device__ unsigned g_int_done;   // +64 per launch: intersections written
__device__ unsigned g_spec_done;  // +11 per launch: speculative xm built
__device__ unsigned g_cold_done;  // +1  per launch IF cache path: xm rebuilt

// Sleep-poll until *addr >= target (acquire).
__device__ __forceinline__ void poll_ge(const unsigned* addr, unsigned target) {
    unsigned cur;
    for (;;) {
        asm volatile("ld.acquire.gpu.u32 %0, [%1];"
                     : "=r"(cur) : "l"(addr) : "memory");
        if (cur >= target) break;
        __nanosleep(64);
    }
}

// 1024-thread block inclusive scan (one int per thread).
__device__ __forceinline__ int scan1024(int v, int lane, int wid, int* sbuf) {
    __syncthreads();
    #pragma unroll
    for (int o = 1; o < 32; o <<= 1) {
        int t = __shfl_up_sync(0xffffffffu, v, o);
        if (lane >= o) v += t;
    }
    if (lane == 31) sbuf[wid] = v;
    __syncthreads();
    if (wid == 0) {
        int w = sbuf[lane];
        #pragma unroll
        for (int o = 1; o < 32; o <<= 1) {
            int t = __shfl_up_sync(0xffffffffu, w, o);
            if (lane >= o) w += t;
        }
        sbuf[lane] = w;
    }
    __syncthreads();
    if (wid > 0) v += sbuf[wid - 1];
    return v;
}

// ============================================================================
// Mega-kernel, ONE launch, 128 blocks x 1024 threads, counter-released phases:
//   block 0:       smem radix select -> maskbits -> g_mask_done++
//   blocks 1..64:  cbits (concurrent) -> poll mask -> intersection -> g_int_done++
//   blocks 65..75: poll mask -> SPECULATIVE xm = mask (x)  -> g_spec_done++
//   ALL:           poll int==64 && spec==11 -> local decision ->
//                  hot path: GEMV immediately | cold path: block 0 rebuilds xm
// ============================================================================
__global__ void __launch_bounds__(TPB, 1)
mega_kernel(const float* __restrict__ x, const int* __restrict__ cached,
            const float* __restrict__ W, const float* __restrict__ bias,
            float* __restrict__ out) {
    __shared__ unsigned s_mem[N_IN];     // block 0: |x| bits; blocks 1-64: cbits
    __shared__ unsigned hist[2048];
    __shared__ unsigned s_bits[NBW];
    __shared__ int scanbuf[32];
    __shared__ int s_b, s_G, s_need, s_use, s_best;
    __shared__ unsigned s_T, s_gen;

    const int b = blockIdx.x, tid = threadIdx.x;
    const int lane = tid & 31, wid = tid >> 5;

    if (tid == 0) s_gen = atomicAdd(&g_arrive, 1u) / GRID;   // launch generation
    __syncthreads();
    const unsigned gen = s_gen;

    if (b == 0) {
        // ---- fused vectorized stage + level-0 histogram (bits [30:21]) ----
        for (int i = tid; i < 2048; i += TPB) hist[i] = 0;
        for (int i = tid; i < NBW; i += TPB) s_bits[i] = 0;
        __syncthreads();
        {
            const uint4* x4u = (const uint4*)x;       // 2752 vec4 total
            uint4* s4 = (uint4*)s_mem;
            for (int i = tid; i < N_IN / 4; i += TPB) {
                uint4 u = x4u[i];
                u.x &= 0x7FFFFFFFu; u.y &= 0x7FFFFFFFu;
                u.z &= 0x7FFFFFFFu; u.w &= 0x7FFFFFFFu;
                s4[i] = u;
                atomicAdd(&hist[u.x >> 21], 1u);
                atomicAdd(&hist[u.y >> 21], 1u);
                atomicAdd(&hist[u.z >> 21], 1u);
                atomicAdd(&hist[u.w >> 21], 1u);
            }
        }
        __syncthreads();
        {
            const int j0 = 2047 - 2 * tid, j1 = j0 - 1;
            const int h0 = hist[j0], h1 = hist[j1];
            int S = scan1024(h0 + h1, lane, wid, scanbuf);
            int excl = S - h0 - h1;
            const int Kr = TOPK_K;
            if (excl + h0 >= Kr && excl < Kr)   { s_b = j0; s_G = excl; }
            else if (S >= Kr && excl + h0 < Kr) { s_b = j1; s_G = excl + h0; }
        }
        __syncthreads();
        const int b0 = s_b, G0 = s_G;

        // ---- level 1: bits [20:10] ----
        __syncthreads();
        for (int i = tid; i < 2048; i += TPB) hist[i] = 0;
        __syncthreads();
        for (int i = tid; i < N_IN; i += TPB) {
            unsigned u = s_mem[i];
            if ((int)(u >> 21) == b0) atomicAdd(&hist[(u >> 10) & 0x7FF], 1u);
        }
        __syncthreads();
        {
            const int j0 = 2047 - 2 * tid, j1 = j0 - 1;
            const int h0 = hist[j0], h1 = hist[j1];
            int S = scan1024(h0 + h1, lane, wid, scanbuf);
            int excl = S - h0 - h1;
            const int Kr = TOPK_K - G0;
            if (excl + h0 >= Kr && excl < Kr)   { s_b = j0; s_G = G0 + excl; }
            else if (S >= Kr && excl + h0 < Kr) { s_b = j1; s_G = G0 + excl + h0; }
        }
        __syncthreads();
        const int b1 = s_b, G1 = s_G;

        // ---- level 2: bits [9:0] ----
        __syncthreads();
        for (int i = tid; i < 2048; i += TPB) hist[i] = 0;
        __syncthreads();
        const unsigned top22 = ((unsigned)b0 << 21) | ((unsigned)b1 << 10);
        for (int i = tid; i < N_IN; i += TPB) {
            unsigned u = s_mem[i];
            if ((u & 0xFFFFFC00u) == top22) atomicAdd(&hist[u & 0x3FF], 1u);
        }
        __syncthreads();
        {
            const int j = 1023 - tid;
            const int h = (int)hist[j];
            int S = scan1024(h, lane, wid, scanbuf);
            int excl = S - h;
            const int Kr = TOPK_K - G1;
            if (S >= Kr && excl < Kr) { s_T = top22 | (unsigned)j; s_need = Kr - excl; }
        }
        __syncthreads();
        const unsigned T = s_T;
        const int need = s_need;

        // ---- mask build with smallest-index tie-break ----
        const int CHUNK = (N_IN + TPB - 1) / TPB;   // 11
        const int start = tid * CHUNK;
        const int end   = min(start + CHUNK, N_IN);

        int tieCnt = 0;
        for (int i = start; i < end; i++)
            if (s_mem[i] == T) tieCnt++;
        int incl = scan1024(tieCnt, lane, wid, scanbuf);
        int rank = incl - tieCnt;

        for (int i = start; i < end; i++) {
            unsigned u = s_mem[i];
            bool sel;
            if (u > T)       sel = true;
            else if (u == T) { sel = (rank < need); rank++; }
            else             sel = false;
            if (sel) atomicOr(&s_bits[i >> 5], 1u << (i & 31));
        }
        __syncthreads();
        for (int i = tid; i < NBW; i += TPB) g_maskbits[i] = s_bits[i];
        __syncthreads();
        if (tid == 0) {
            __threadfence();
            atomicAdd(&g_mask_done, 1u);            // release maskbits
        }
    } else if (b <= 64) {
        // ---- cache bitset for cache (b-1), fully concurrent with select ----
        for (int i = tid; i < NBW; i += TPB) s_mem[i] = 0;
        __syncthreads();
        const int* row = cached + (b - 1) * TOPK_K;
        for (int k = tid; k < TOPK_K; k += TPB) {
            int idx = row[k];
            atomicOr(&s_mem[idx >> 5], 1u << (idx & 31));
        }
        __syncthreads();

        if (tid == 0) poll_ge(&g_mask_done, gen + 1u);
        __syncthreads();

        // ---- deduped intersection ----
        int cnt = 0;
        for (int i = tid; i < NBW; i += TPB)
            cnt += __popc(s_mem[i] & g_maskbits[i]);
        #pragma unroll
        for (int o = 16; o; o >>= 1) cnt += __shfl_down_sync(0xffffffffu, cnt, o);
        __syncthreads();
        if (lane == 0) scanbuf[wid] = cnt;
        __syncthreads();
        if (tid == 0) {
            int s = 0;
            #pragma unroll
            for (int i = 0; i < 32; i++) s += scanbuf[i];
            g_inter[b - 1] = s;
            __threadfence();
            atomicAdd(&g_int_done, 1u);             // one of 64
        }
    } else if (b <= 75) {
        // ---- speculative xm = mask (x) by 11 idle blocks (hot path) ----
        if (tid == 0) poll_ge(&g_mask_done, gen + 1u);
        __syncthreads();
        const int gi = (b - 65) * TPB + tid;
        if (gi < N_IN) {
            int sel = (g_maskbits[gi >> 5] >> (gi & 31)) & 1;
            g_xm[gi] = sel ? x[gi] : 0.0f;
        }
        __syncthreads();
        if (tid == 0) {
            __threadfence();
            atomicAdd(&g_spec_done, 1u);            // one of 11
        }
    }

    // ---- ALL blocks: wait for intersections + speculative xm; decide ----
    if (tid == 0) {
        poll_ge(&g_int_done, (gen + 1u) * 64u);
        poll_ge(&g_spec_done, (gen + 1u) * 11u);
        float best = -1.0f; int bi = 0;
        #pragma unroll
        for (int i = 0; i < N_CACHE; i++) {
            float r = (float)g_inter[i] / (float)TOPK_K;
            if (r > best) { best = r; bi = i; }     // first-max = argmax
        }
        s_use  = (best >= 0.9f) ? 1 : 0;
        s_best = bi;
    }
    __syncthreads();

    // ---- cold path only: block 0 rebuilds xm with multiplicities ----
    if (s_use) {
        if (b == 0) {
            for (int i = tid; i < N_IN; i += TPB) g_xm[i] = 0.0f;
            __syncthreads();
            const int* brow = cached + s_best * TOPK_K;
            for (int k = tid; k < TOPK_K; k += TPB) {
                int idx = brow[k];
                atomicAdd(&g_xm[idx], x[idx]);      // duplicates = multiplicity
            }
            __syncthreads();
            if (tid == 0) {
                __threadfence();
                atomicAdd(&g_cold_done, 1u);
            }
        }
        if (tid == 0) poll_ge(&g_cold_done, gen + 1u);
        __syncthreads();
    }

    // ---- GEMV: exact R4 pattern — 1 row/warp, 4096 x 44KB streams ----
    const int row = b * 32 + wid;                // 0..4095
    const float4* __restrict__ w4 = (const float4*)(W + (long long)row * N_IN);
    const float4* __restrict__ x4 = (const float4*)g_xm;

    float a0 = 0.0f, a1 = 0.0f;
    #pragma unroll 4
    for (int it = 0; it < 43; it++) {
        const int j = lane + it * 64;
        float4 w  = __ldcs(w4 + j);
        float4 v  = x4[j];
        a0 += w.x * v.x + w.y * v.y;
        a1 += w.z * v.z + w.w * v.w;
        float4 w2 = __ldcs(w4 + j + 32);
        float4 v2 = x4[j + 32];
        a0 += w2.x * v2.x + w2.y * v2.y;
        a1 += w2.z * v2.z + w2.w * v2.w;
    }
    float acc = a0 + a1;
    #pragma unroll
    for (int o = 16; o; o >>= 1) acc += __shfl_down_sync(0xffffffffu, acc, o);
    if (lane == 0) out[row] = acc + bias[row];
}

// ============================================================================
extern "C" void kernel_launch(void* const* d_in, const int* in_sizes, int n_in,
                              void* d_out, int out_size) {
    const float* x      = (const float*)d_in[0];
    const float* W      = (const float*)d_in[1];
    const float* bias   = (const float*)d_in[2];
    const int*   cached = (const int*)d_in[3];
    float*       out    = (float*)d_out;

    mega_kernel<<<GRID, TPB>>>(x, cached, W, bias, out);
}

// round 16
// speedup vs baseline: 1.2369x; 1.0099x over previous
#include <cuda_runtime.h>
#include <cuda_bf16.h>

#define N_IN    11008
#define N_OUT   4096
#define TOPK_K  5504
#define N_CACHE 64
#define NBW     344            // ceil(11008/32)
#define TPB     1024
#define GRID    128            // 128 blocks x 32 warps = 4096 warps = 1 row/warp

// ---- device-global scratch (allocation-free; fully rewritten each call) ----
__device__ __align__(16) float g_xm2[N_IN];   // cold-path xm (multiplicities)
__device__ unsigned g_maskbits[NBW];
__device__ int g_inter[N_CACHE];
__device__ unsigned g_decide_val;  // (use<<31)|best, valid when decide_done hits
__device__ unsigned g_arrive;      // launch arrival counter (monotonic)
__device__ unsigned g_mask_done;   // +1 per launch: maskbits published
__device__ unsigned g_int_done;    // +64 per launch: intersections written
__device__ unsigned g_decide_done; // +1 per launch: decision published
__device__ unsigned g_cold_done;   // +1 per launch IF cold path: xm2 built

// Sleep-poll until *addr >= target (acquire).
__device__ __forceinline__ void poll_ge(const unsigned* addr, unsigned target) {
    unsigned cur;
    for (;;) {
        asm volatile("ld.acquire.gpu.u32 %0, [%1];"
                     : "=r"(cur) : "l"(addr) : "memory");
        if (cur >= target) break;
        __nanosleep(64);
    }
}

// 1024-thread block inclusive scan (one int per thread).
__device__ __forceinline__ int scan1024(int v, int lane, int wid, int* sbuf) {
    __syncthreads();
    #pragma unroll
    for (int o = 1; o < 32; o <<= 1) {
        int t = __shfl_up_sync(0xffffffffu, v, o);
        if (lane >= o) v += t;
    }
    if (lane == 31) sbuf[wid] = v;
    __syncthreads();
    if (wid == 0) {
        int w = sbuf[lane];
        #pragma unroll
        for (int o = 1; o < 32; o <<= 1) {
            int t = __shfl_up_sync(0xffffffffu, w, o);
            if (lane >= o) w += t;
        }
        sbuf[lane] = w;
    }
    __syncthreads();
    if (wid > 0) v += sbuf[wid - 1];
    return v;
}

// ============================================================================
// Mega-kernel, ONE launch, 128 blocks x 1024 threads:
//   block 0:       smem radix select -> maskbits -> g_mask_done++
//   blocks 1..64:  cbits (concurrent) -> poll mask -> intersection -> g_int_done++
//   block 65:      poll int==64 -> decision -> g_decide_done++ (+xm2 if cold)
//   ALL blocks:    poll mask -> GEMV with ON-THE-FLY bitmask on raw x
//                  -> read decision (long since ready) -> store (hot)
//                  or recompute from g_xm2 (cold) -> store
// ============================================================================
__global__ void __launch_bounds__(TPB, 1)
mega_kernel(const float* __restrict__ x, const int* __restrict__ cached,
            const float* __restrict__ W, const float* __restrict__ bias,
            float* __restrict__ out) {
    __shared__ unsigned s_mem[N_IN];     // block 0: |x| bits; blocks 1-64: cbits
    __shared__ unsigned hist[2048];
    __shared__ unsigned s_bits[NBW];
    __shared__ int scanbuf[32];
    __shared__ int s_b, s_G, s_need;
    __shared__ unsigned s_T, s_gen, s_dec;

    const int b = blockIdx.x, tid = threadIdx.x;
    const int lane = tid & 31, wid = tid >> 5;

    if (tid == 0) s_gen = atomicAdd(&g_arrive, 1u) / GRID;   // launch generation
    __syncthreads();
    const unsigned gen = s_gen;

    if (b == 0) {
        // ---- fused vectorized stage + level-0 histogram (bits [30:21]) ----
        for (int i = tid; i < 2048; i += TPB) hist[i] = 0;
        for (int i = tid; i < NBW; i += TPB) s_bits[i] = 0;
        __syncthreads();
        {
            const uint4* x4u = (const uint4*)x;       // 2752 vec4 total
            uint4* s4 = (uint4*)s_mem;
            for (int i = tid; i < N_IN / 4; i += TPB) {
                uint4 u = x4u[i];
                u.x &= 0x7FFFFFFFu; u.y &= 0x7FFFFFFFu;
                u.z &= 0x7FFFFFFFu; u.w &= 0x7FFFFFFFu;
                s4[i] = u;
                atomicAdd(&hist[u.x >> 21], 1u);
                atomicAdd(&hist[u.y >> 21], 1u);
                atomicAdd(&hist[u.z >> 21], 1u);
                atomicAdd(&hist[u.w >> 21], 1u);
            }
        }
        __syncthreads();
        {
            const int j0 = 2047 - 2 * tid, j1 = j0 - 1;
            const int h0 = hist[j0], h1 = hist[j1];
            int S = scan1024(h0 + h1, lane, wid, scanbuf);
            int excl = S - h0 - h1;
            const int Kr = TOPK_K;
            if (excl + h0 >= Kr && excl < Kr)   { s_b = j0; s_G = excl; }
            else if (S >= Kr && excl + h0 < Kr) { s_b = j1; s_G = excl + h0; }
        }
        __syncthreads();
        const int b0 = s_b, G0 = s_G;

        // ---- level 1: bits [20:10] ----
        __syncthreads();
        for (int i = tid; i < 2048; i += TPB) hist[i] = 0;
        __syncthreads();
        for (int i = tid; i < N_IN; i += TPB) {
            unsigned u = s_mem[i];
            if ((int)(u >> 21) == b0) atomicAdd(&hist[(u >> 10) & 0x7FF], 1u);
        }
        __syncthreads();
        {
            const int j0 = 2047 - 2 * tid, j1 = j0 - 1;
            const int h0 = hist[j0], h1 = hist[j1];
            int S = scan1024(h0 + h1, lane, wid, scanbuf);
            int excl = S - h0 - h1;
            const int Kr = TOPK_K - G0;
            if (excl + h0 >= Kr && excl < Kr)   { s_b = j0; s_G = G0 + excl; }
            else if (S >= Kr && excl + h0 < Kr) { s_b = j1; s_G = G0 + excl + h0; }
        }
        __syncthreads();
        const int b1 = s_b, G1 = s_G;

        // ---- level 2: bits [9:0] ----
        __syncthreads();
        for (int i = tid; i < 2048; i += TPB) hist[i] = 0;
        __syncthreads();
        const unsigned top22 = ((unsigned)b0 << 21) | ((unsigned)b1 << 10);
        for (int i = tid; i < N_IN; i += TPB) {
            unsigned u = s_mem[i];
            if ((u & 0xFFFFFC00u) == top22) atomicAdd(&hist[u & 0x3FF], 1u);
        }
        __syncthreads();
        {
            const int j = 1023 - tid;
            const int h = (int)hist[j];
            int S = scan1024(h, lane, wid, scanbuf);
            int excl = S - h;
            const int Kr = TOPK_K - G1;
            if (S >= Kr && excl < Kr) { s_T = top22 | (unsigned)j; s_need = Kr - excl; }
        }
        __syncthreads();
        const unsigned T = s_T;
        const int need = s_need;

        // ---- mask build with smallest-index tie-break ----
        const int CHUNK = (N_IN + TPB - 1) / TPB;   // 11
        const int start = tid * CHUNK;
        const int end   = min(start + CHUNK, N_IN);

        int tieCnt = 0;
        for (int i = start; i < end; i++)
            if (s_mem[i] == T) tieCnt++;
        int incl = scan1024(tieCnt, lane, wid, scanbuf);
        int rank = incl - tieCnt;

        for (int i = start; i < end; i++) {
            unsigned u = s_mem[i];
            bool sel;
            if (u > T)       sel = true;
            else if (u == T) { sel = (rank < need); rank++; }
            else             sel = false;
            if (sel) atomicOr(&s_bits[i >> 5], 1u << (i & 31));
        }
        __syncthreads();
        for (int i = tid; i < NBW; i += TPB) g_maskbits[i] = s_bits[i];
        __syncthreads();
        if (tid == 0) {
            __threadfence();
            atomicAdd(&g_mask_done, 1u);            // release maskbits
        }
    } else if (b <= 64) {
        // ---- cache bitset for cache (b-1), fully concurrent with select ----
        for (int i = tid; i < NBW; i += TPB) s_mem[i] = 0;
        __syncthreads();
        const int* row = cached + (b - 1) * TOPK_K;
        for (int k = tid; k < TOPK_K; k += TPB) {
            int idx = row[k];
            atomicOr(&s_mem[idx >> 5], 1u << (idx & 31));
        }
        __syncthreads();

        if (tid == 0) poll_ge(&g_mask_done, gen + 1u);
        __syncthreads();

        // ---- deduped intersection ----
        int cnt = 0;
        for (int i = tid; i < NBW; i += TPB)
            cnt += __popc(s_mem[i] & g_maskbits[i]);
        #pragma unroll
        for (int o = 16; o; o >>= 1) cnt += __shfl_down_sync(0xffffffffu, cnt, o);
        __syncthreads();
        if (lane == 0) scanbuf[wid] = cnt;
        __syncthreads();
        if (tid == 0) {
            int s = 0;
            #pragma unroll
            for (int i = 0; i < 32; i++) s += scanbuf[i];
            g_inter[b - 1] = s;
            __threadfence();
            atomicAdd(&g_int_done, 1u);             // one of 64
        }
    } else if (b == 65) {
        // ---- decision block: runs concurrently with everyone's GEMV ----
        if (tid == 0) {
            poll_ge(&g_int_done, (gen + 1u) * 64u);
            float best = -1.0f; int bi = 0;
            #pragma unroll
            for (int i = 0; i < N_CACHE; i++) {
                float r = (float)g_inter[i] / (float)TOPK_K;
                if (r > best) { best = r; bi = i; } // first-max = argmax
            }
            unsigned use = (best >= 0.9f) ? 1u : 0u;
            s_dec = (use << 31) | (unsigned)bi;
            asm volatile("st.release.gpu.u32 [%0], %1;"
                         :: "l"(&g_decide_val), "r"(s_dec) : "memory");
            __threadfence();
            atomicAdd(&g_decide_done, 1u);          // decision published
        }
        __syncthreads();
        // cold path: build xm2 with multiplicities, then release
        if (s_dec >> 31) {
            for (int i = tid; i < N_IN; i += TPB) g_xm2[i] = 0.0f;
            __syncthreads();
            const int* brow = cached + (s_dec & 0x7FFFFFFFu) * TOPK_K;
            for (int k = tid; k < TOPK_K; k += TPB) {
                int idx = brow[k];
                atomicAdd(&g_xm2[idx], x[idx]);     // duplicates = multiplicity
            }
            __syncthreads();
            if (tid == 0) {
                __threadfence();
                atomicAdd(&g_cold_done, 1u);
            }
        }
    }

    // ---- ALL blocks: wait only for the MASK, then GEMV on raw x + bitmask ----
    if (tid == 0) poll_ge(&g_mask_done, gen + 1u);
    __syncthreads();

    const int row = b * 32 + wid;                // 0..4095
    const float4* __restrict__ w4 = (const float4*)(W + (long long)row * N_IN);
    const float4* __restrict__ x4 = (const float4*)x;
    const unsigned* __restrict__ mb = g_maskbits;

    float a0 = 0.0f, a1 = 0.0f;
    #pragma unroll 4
    for (int it = 0; it < 43; it++) {
        const int j = lane + it * 64;            // float4 index; elems 4j..4j+3
        float4 w  = __ldcs(w4 + j);
        float4 v  = x4[j];
        unsigned m0 = mb[j >> 3];                // word holding bits 4j..4j+3
        const unsigned sh = (4 * j) & 31;        // same shift for j and j+32
        float4 w2 = __ldcs(w4 + j + 32);
        float4 v2 = x4[j + 32];
        unsigned m1 = mb[(j >> 3) + 4];
        a0 += ((m0 >> (sh + 0)) & 1u ? w.x * v.x : 0.0f)
            + ((m0 >> (sh + 1)) & 1u ? w.y * v.y : 0.0f);
        a1 += ((m0 >> (sh + 2)) & 1u ? w.z * v.z : 0.0f)
            + ((m0 >> (sh + 3)) & 1u ? w.w * v.w : 0.0f);
        a0 += ((m1 >> (sh + 0)) & 1u ? w2.x * v2.x : 0.0f)
            + ((m1 >> (sh + 1)) & 1u ? w2.y * v2.y : 0.0f);
        a1 += ((m1 >> (sh + 2)) & 1u ? w2.z * v2.z : 0.0f)
            + ((m1 >> (sh + 3)) & 1u ? w2.w * v2.w : 0.0f);
    }
    float acc = a0 + a1;
    #pragma unroll
    for (int o = 16; o; o >>= 1) acc += __shfl_down_sync(0xffffffffu, acc, o);

    // ---- decision check (computed ~2us into the 35us GEMV: instant poll) ----
    if (tid == 0) {
        poll_ge(&g_decide_done, gen + 1u);
        unsigned d;
        asm volatile("ld.acquire.gpu.u32 %0, [%1];"
                     : "=r"(d) : "l"(&g_decide_val) : "memory");
        s_dec = d;
    }
    __syncthreads();

    if (!(s_dec >> 31)) {
        if (lane == 0) out[row] = acc + bias[row];   // hot path
    } else {
        // cold path: recompute from xm2 (multiplicity-weighted)
        if (tid == 0) poll_ge(&g_cold_done, gen + 1u);
        __syncthreads();
        const float4* __restrict__ x4b = (const float4*)g_xm2;
        float c0 = 0.0f, c1 = 0.0f;
        #pragma unroll 4
        for (int it = 0; it < 43; it++) {
            const int j = lane + it * 64;
            float4 w  = w4[j];
            float4 v  = x4b[j];
            c0 += w.x * v.x + w.y * v.y;
            c1 += w.z * v.z + w.w * v.w;
            float4 w2 = w4[j + 32];
            float4 v2 = x4b[j + 32];
            c0 += w2.x * v2.x + w2.y * v2.y;
            c1 += w2.z * v2.z + w2.w * v2.w;
        }
        float cacc = c0 + c1;
        #pragma unroll
        for (int o = 16; o; o >>= 1) cacc += __shfl_down_sync(0xffffffffu, cacc, o);
        if (lane == 0) out[row] = cacc + bias[row];
    }
}

// ============================================================================
extern "C" void kernel_launch(void* const* d_in, const int* in_sizes, int n_in,
                              void* d_out, int out_size) {
    const float* x      = (const float*)d_in[0];
    const float* W      = (const float*)d_in[1];
    const float* bias   = (const float*)d_in[2];
    const int*   cached = (const int*)d_in[3];
    float*       out    = (float*)d_out;

    mega_kernel<<<GRID, TPB>>>(x, cached, W, bias, out);
}